// round 15
// baseline (speedup 1.0000x reference)
#include <cuda_runtime.h>
#include <cuda_bf16.h>
#include <cstdint>

// NnInteractionTokenizer: bond = x[row]*x[col]; local_field = segsum(bond, row);
// tokens = relu(relu([x, lf] @ w1^T + b1) @ w2^T + b2)
//
// local_field[r] = x[r] * sum_{e: row[e]=r} x[col[e]] -> edge phase only
// accumulates x[col[e]] into g_acc[row[e]]; x[r] multiply folds into node phase.
//
// R15: fused persistent kernel at the R11 edge operating point.
//   grid 1184 = 8 CTAs/SM x 148 SMs, 256 thr, __launch_bounds__(256,8) ->
//   <=32 regs, RF exactly fits, ALL CTAs wave-1 resident -> spin grid barrier
//   is deadlock-free. Edge inner loop byte-identical to R11 (measured ~50us =
//   L1tex wavefront floor: 264 wf/warp x 338 warps/SM ~ 89K cyc). After the
//   barrier the node phase runs in-kernel: weights pre-staged in smem (before
//   edge), g_acc L2-hot, no 2nd launch, no cold prologue.
//
// Replay safety: g_acc zeroed at module load and re-zeroed by the SAME thread
// that reads it in the node phase. g_bar is a monotonic arrival counter
// (never reset; target derived from pre-increment value) -> graph-replay-safe.

#define N_NODES 100000
#define N_EDGES 6400000
#define TD 16
#define EPT 4
#define BLK 256
#define GRID 1184                                   // 8 * 148, exactly 1 wave
#define CHUNK (BLK * EPT)                           // 1024 edges
#define NCHUNKS (N_EDGES / CHUNK)                   // 6250 (exact)

__device__ float g_acc[N_NODES];
__device__ unsigned int g_bar;                      // monotonic across replays

__global__ void __launch_bounds__(BLK, 8)
fused_kernel(const void* __restrict__ ei, const float* __restrict__ x,
             const float* __restrict__ w1, const float* __restrict__ b1,
             const float* __restrict__ w2, const float* __restrict__ b2,
             float* __restrict__ out) {
    __shared__ float sw1[2 * TD];
    __shared__ float sb1[TD];
    __shared__ __align__(16) float sw2[TD * TD];
    __shared__ float sb2[TD];
    __shared__ int s_is64;

    const int t = threadIdx.x;

    // Stage MLP weights now — overlaps the entire edge phase.
    if (t < 2 * TD) sw1[t] = w1[t];
    if (t < TD) { sb1[t] = b1[t]; sb2[t] = b2[t]; }
    sw2[t] = w2[t];                                 // BLK == 256 == TD*TD

    // Dtype probe (uniform): reference asks int64 but JAX w/o x64 yields int32
    // (confirmed: measured HBM traffic ~51MB). As uint32 words, int64 data
    // (<2^17, LE) has odd words == 0; int32 has random words ->
    // P(8 specific odd words all zero) ~ 1e-40. All CTAs read the SAME words.
    if (t == 0) {
        const unsigned int* w = (const unsigned int*)ei;
        unsigned int acc = 0;
#pragma unroll
        for (int k = 0; k < 8; k++) acc |= w[2 * k + 1];
        s_is64 = (acc == 0u) ? 1 : 0;
    }
    __syncthreads();
    const int is64 = s_is64;

    // ---------------- edge phase: R11 inner body, chunk-strided -------------
    // CTA->SM map is bid%148 round-robin, so the 330 extra-chunk CTAs spread
    // across all SMs (per-SM imbalance ~ +2%).
    for (int ch = blockIdx.x; ch < NCHUNKS; ch += GRID) {
        const long long base = (long long)ch * CHUNK + (long long)t * EPT;

        if (!is64) {
            const int4* row = (const int4*)ei;
            const int4* col = row + (N_EDGES / 4);
            int4 rv = __ldg(&row[base / 4]);
            int4 cv = __ldg(&col[base / 4]);

            float v0 = __ldg(&x[cv.x]);
            float v1 = __ldg(&x[cv.y]);
            float v2 = __ldg(&x[cv.z]);
            float v3 = __ldg(&x[cv.w]);

            atomicAdd(&g_acc[rv.x], v0);
            atomicAdd(&g_acc[rv.y], v1);
            atomicAdd(&g_acc[rv.z], v2);
            atomicAdd(&g_acc[rv.w], v3);
        } else {
            const longlong2* row = (const longlong2*)ei;       // edge_index[0]
            const longlong2* col = row + (N_EDGES / 2);        // edge_index[1]
            longlong2 r0 = __ldg(&row[base / 2]);
            longlong2 r1 = __ldg(&row[base / 2 + 1]);
            longlong2 c0 = __ldg(&col[base / 2]);
            longlong2 c1 = __ldg(&col[base / 2 + 1]);

            float v0 = __ldg(&x[(int)c0.x]);
            float v1 = __ldg(&x[(int)c0.y]);
            float v2 = __ldg(&x[(int)c1.x]);
            float v3 = __ldg(&x[(int)c1.y]);

            atomicAdd(&g_acc[(int)r0.x], v0);
            atomicAdd(&g_acc[(int)r0.y], v1);
            atomicAdd(&g_acc[(int)r1.x], v2);
            atomicAdd(&g_acc[(int)r1.y], v3);
        }
    }

    // ---------------- grid barrier (monotonic counter, replay-safe) ---------
    __threadfence();                 // publish this thread's REDs
    __syncthreads();
    if (t == 0) {
        unsigned int old = atomicAdd(&g_bar, 1u);
        unsigned int target = old - (old % GRID) + GRID;
        volatile unsigned int* p = &g_bar;
        while ((int)(*p - target) < 0) { }
    }
    __syncthreads();
    __threadfence();                 // order g_acc loads after release

    // ---------------- node phase: 1 thread per node -------------------------
    const int n = blockIdx.x * BLK + t;
    if (n >= N_NODES) return;

    const float s   = x[n];
    const float lfa = g_acc[n];
    g_acc[n] = 0.0f;                 // same thread, same address: ordered

    const float lf = s * lfa;

    float h[TD];
#pragma unroll
    for (int j = 0; j < TD; j++) {
        float v = fmaf(sw1[2 * j + 1], lf, fmaf(sw1[2 * j], s, sb1[j]));
        h[j] = v > 0.f ? v : 0.f;
    }

    float4* o = (float4*)(out + (size_t)n * TD);
#pragma unroll
    for (int k4 = 0; k4 < 4; k4++) {
        float4 res;
        float* rp = (float*)&res;
#pragma unroll
        for (int kk = 0; kk < 4; kk++) {
            const int k = k4 * 4 + kk;
            float v = sb2[k];
            const float4* wrow = (const float4*)&sw2[k * TD];
#pragma unroll
            for (int j4 = 0; j4 < 4; j4++) {
                float4 w = wrow[j4];
                v = fmaf(w.x, h[j4 * 4 + 0], v);
                v = fmaf(w.y, h[j4 * 4 + 1], v);
                v = fmaf(w.z, h[j4 * 4 + 2], v);
                v = fmaf(w.w, h[j4 * 4 + 3], v);
            }
            rp[kk] = v > 0.f ? v : 0.f;
        }
        o[k4] = res;
    }
}

extern "C" void kernel_launch(void* const* d_in, const int* in_sizes, int n_in,
                              void* d_out, int out_size) {
    const float* x  = (const float*)d_in[0];
    const void*  ei = d_in[1];
    const float* w1 = (const float*)d_in[2];
    const float* b1 = (const float*)d_in[3];
    const float* w2 = (const float*)d_in[4];
    const float* b2 = (const float*)d_in[5];
    float* out = (float*)d_out;

    fused_kernel<<<GRID, BLK>>>(ei, x, w1, b1, w2, b2, out);
}

// round 17
// speedup vs baseline: 1.1499x; 1.1499x over previous
#include <cuda_runtime.h>
#include <cuda_bf16.h>
#include <cstdint>

// NnInteractionTokenizer: bond = x[row]*x[col]; local_field = segsum(bond, row);
// tokens = relu(relu([x, lf] @ w1^T + b1) @ w2^T + b2)
//
// local_field[r] = x[r] * sum_{e: row[e]=r} x[col[e]] -> edge phase only
// accumulates x[col[e]] into g_acc[row[e]]; x[r] multiply folds into node phase.
//
// Structure (measured-validated): two kernels. Persistent/fused variants are
// 0-for-2 (R9, R15): a grid-stride loop at 32 regs cannot pipeline across
// iterations, while one-shot CTAs get free pipelining from warp churn.
//   edge: R11-exact (256thr x 8 CTA/SM, batched int4 idx loads, batched
//         divergent gathers, 4x REDG.F32) — ~50us L1tex wavefront floor.
//   node: NEW — layer2 via 16 independent accumulator chains using packed
//         fma.rn.f32x2 (FFMA2): 16x(2 LDS.128 + 8 FFMA2) vs 64 LDS + 256
//         serial-chain FMA. PDL overlaps its prologue with the edge tail.
//
// g_acc invariant: __device__ globals start zeroed; node re-zeroes g_acc[n]
// from the SAME thread that read it -> zero at entry of every graph replay.

#define N_NODES 100000
#define N_EDGES 6400000
#define TD 16
#define EPT 4

__device__ float g_acc[N_NODES];

// ---------------------------------------------------------------------------
// Edge phase: EPT edges/thread; vectorized index loads (DRAM stream), batched
// divergent gathers (L1/L2), EPT fire-and-forget REDG.F32 into g_acc.
//
// Dtype probe (per block, uniform): reference asks int64 but JAX w/o x64
// yields int32 (confirmed: measured HBM traffic ~51MB). As uint32 words,
// int64 data (<2^17, LE) has odd words == 0; int32 data has random words ->
// P(8 specific odd words all zero) ~ 1e-40. All blocks read the SAME 8 words.
// ---------------------------------------------------------------------------
__global__ void __launch_bounds__(256, 8) edge_kernel(const void* __restrict__ ei,
                                                      const float* __restrict__ x) {
#if (__CUDACC_VER_MAJOR__ >= 12)
    cudaTriggerProgrammaticLaunchCompletion();
#endif
    __shared__ int s_is64;
    if (threadIdx.x == 0) {
        const unsigned int* w = (const unsigned int*)ei;
        unsigned int acc = 0;
#pragma unroll
        for (int k = 0; k < 8; k++) acc |= w[2 * k + 1];
        s_is64 = (acc == 0u) ? 1 : 0;
    }
    __syncthreads();

    const int tid = blockIdx.x * blockDim.x + threadIdx.x;
    const long long base = (long long)tid * EPT;
    if (base >= N_EDGES) return;

    if (!s_is64) {
        const int4* row = (const int4*)ei;
        const int4* col = row + (N_EDGES / 4);
        int4 rv = __ldg(&row[base / 4]);
        int4 cv = __ldg(&col[base / 4]);

        float v0 = __ldg(&x[cv.x]);
        float v1 = __ldg(&x[cv.y]);
        float v2 = __ldg(&x[cv.z]);
        float v3 = __ldg(&x[cv.w]);

        atomicAdd(&g_acc[rv.x], v0);
        atomicAdd(&g_acc[rv.y], v1);
        atomicAdd(&g_acc[rv.z], v2);
        atomicAdd(&g_acc[rv.w], v3);
    } else {
        const longlong2* row = (const longlong2*)ei;
        const longlong2* col = row + (N_EDGES / 2);
        longlong2 r0 = __ldg(&row[base / 2]);
        longlong2 r1 = __ldg(&row[base / 2 + 1]);
        longlong2 c0 = __ldg(&col[base / 2]);
        longlong2 c1 = __ldg(&col[base / 2 + 1]);

        float v0 = __ldg(&x[(int)c0.x]);
        float v1 = __ldg(&x[(int)c0.y]);
        float v2 = __ldg(&x[(int)c1.x]);
        float v3 = __ldg(&x[(int)c1.y]);

        atomicAdd(&g_acc[(int)r0.x], v0);
        atomicAdd(&g_acc[(int)r0.y], v1);
        atomicAdd(&g_acc[(int)r1.x], v2);
        atomicAdd(&g_acc[(int)r1.y], v3);
    }
}

// ---------------------------------------------------------------------------
// Packed fp32x2 helpers (sm_103a FFMA2 — only reachable via PTX).
// Per-lane RN rounding, bit-identical to scalar fmaf.
// ---------------------------------------------------------------------------
__device__ __forceinline__ unsigned long long pack2(float lo, float hi) {
    unsigned long long d;
    asm("mov.b64 %0, {%1, %2};" : "=l"(d) : "f"(lo), "f"(hi));
    return d;
}
__device__ __forceinline__ unsigned long long fma2(unsigned long long a,
                                                   unsigned long long b,
                                                   unsigned long long c) {
    unsigned long long d;
    asm("fma.rn.f32x2 %0, %1, %2, %3;" : "=l"(d) : "l"(a), "l"(b), "l"(c));
    return d;
}
__device__ __forceinline__ void unpack2(unsigned long long v, float& lo, float& hi) {
    asm("mov.b64 {%0, %1}, %2;" : "=f"(lo), "=f"(hi) : "l"(v));
}

// ---------------------------------------------------------------------------
// Node phase: 2->16->16 MLP, 1 thread/node.
// Layer 2 restructured: weights staged TRANSPOSED+PACKED in smem,
//   sw2p[j][k2] = (w2[2*k2][j], w2[2*k2+1][j])  -> for each j, 8 FFMA2 update
// 8 packed accumulators (16 independent chains, no serial reduction tail).
// Per thread: 16 x (2 LDS.128 + 1 pack + 8 FFMA2) ~= 180 instr vs 320 before.
// PDL: prologue (weight staging + x load) overlaps the edge kernel's tail.
// ---------------------------------------------------------------------------
__global__ void __launch_bounds__(256) node_kernel(const float* __restrict__ x,
                                                   const float* __restrict__ w1,
                                                   const float* __restrict__ b1,
                                                   const float* __restrict__ w2,
                                                   const float* __restrict__ b2,
                                                   float* __restrict__ out) {
    __shared__ float sw1[2 * TD];
    __shared__ float sb1[TD];
    __shared__ __align__(16) unsigned long long sw2p[TD][8];  // [j][k2] packed
    __shared__ __align__(16) unsigned long long sb2p[8];      // packed bias

    const int t = threadIdx.x;
    const int n = blockIdx.x * 256 + t;
    const bool act = (n < N_NODES);

    // Prologue (no g_acc access) — overlaps edge tail under PDL.
    float s = 0.f;
    if (act) s = x[n];
    if (t < 2 * TD) sw1[t] = w1[t];
    if (t < TD) sb1[t] = b1[t];
    if (t < 8) sb2p[t] = pack2(b2[2 * t], b2[2 * t + 1]);
    if (t < TD * 8) {                 // 128 threads: j = t>>3, k2 = t&7
        const int j = t >> 3, k2 = t & 7;
        sw2p[j][k2] = pack2(w2[(2 * k2) * TD + j], w2[(2 * k2 + 1) * TD + j]);
    }
    __syncthreads();

#if (__CUDACC_VER_MAJOR__ >= 12)
    cudaGridDependencySynchronize();   // edge grid fully complete
#endif

    float lfa = 0.f;
    if (act) lfa = g_acc[n];
    if (act) g_acc[n] = 0.0f;   // same thread, same address: ordered after read

    const float lf = s * lfa;

    // Layer 1: h = relu(s*w1[:,0] + lf*w1[:,1] + b1)  (16 independent 3-op chains)
    float h[TD];
#pragma unroll
    for (int j = 0; j < TD; j++) {
        float v = fmaf(sw1[2 * j + 1], lf, fmaf(sw1[2 * j], s, sb1[j]));
        h[j] = v > 0.f ? v : 0.f;
    }

    // Layer 2: 8 packed accumulators = 16 independent chains, FFMA2.
    unsigned long long v2[8];
#pragma unroll
    for (int k2 = 0; k2 < 8; k2++) v2[k2] = sb2p[k2];

#pragma unroll
    for (int j = 0; j < TD; j++) {
        const unsigned long long hh = pack2(h[j], h[j]);
        const ulonglong2* wp = (const ulonglong2*)&sw2p[j][0];
#pragma unroll
        for (int i = 0; i < 4; i++) {
            ulonglong2 ww = wp[i];                  // LDS.128: two packed pairs
            v2[2 * i]     = fma2(ww.x, hh, v2[2 * i]);
            v2[2 * i + 1] = fma2(ww.y, hh, v2[2 * i + 1]);
        }
    }

    // Unpack, relu, store as 4x STG.128.
    float4* o = (float4*)(out + (size_t)n * TD);
#pragma unroll
    for (int q = 0; q < 4; q++) {
        float a0, a1, a2, a3;
        unpack2(v2[2 * q],     a0, a1);
        unpack2(v2[2 * q + 1], a2, a3);
        float4 res;
        res.x = a0 > 0.f ? a0 : 0.f;
        res.y = a1 > 0.f ? a1 : 0.f;
        res.z = a2 > 0.f ? a2 : 0.f;
        res.w = a3 > 0.f ? a3 : 0.f;
        if (act) o[q] = res;
    }
}

extern "C" void kernel_launch(void* const* d_in, const int* in_sizes, int n_in,
                              void* d_out, int out_size) {
    const float* x  = (const float*)d_in[0];
    const void*  ei = d_in[1];
    const float* w1 = (const float*)d_in[2];
    const float* b1 = (const float*)d_in[3];
    const float* w2 = (const float*)d_in[4];
    const float* b2 = (const float*)d_in[5];
    float* out = (float*)d_out;

    edge_kernel<<<N_EDGES / EPT / 256, 256>>>(ei, x);

    cudaLaunchConfig_t cfg = {};
    cfg.gridDim  = dim3((N_NODES + 255) / 256, 1, 1);
    cfg.blockDim = dim3(256, 1, 1);
    cudaLaunchAttribute attr[1];
    attr[0].id = cudaLaunchAttributeProgrammaticStreamSerialization;
    attr[0].val.programmaticStreamSerializationAllowed = 1;
    cfg.attrs = attr;
    cfg.numAttrs = 1;
    cudaLaunchKernelEx(&cfg, node_kernel, x, w1, b1, w2, b2, out);
}